// round 1
// baseline (speedup 1.0000x reference)
#include <cuda_runtime.h>
#include <cuda_bf16.h>

#define B 384
#define D 128
#define MARGIN 0.5f

__device__ double g_sum;
__device__ double g_cnt;

__global__ void init_kernel() {
    g_sum = 0.0;
    g_cnt = 0.0;
}

__global__ __launch_bounds__(B) void triplet_kernel(
    const float* __restrict__ emb,
    const int* __restrict__ labels)
{
    __shared__ float ea[D];
    __shared__ float drow[B];
    __shared__ int   slab[B];
    __shared__ float dpos[B];
    __shared__ int   npos;
    __shared__ float rsum[12];
    __shared__ float rcnt[12];

    const int a = blockIdx.x;
    const int t = threadIdx.x;

    if (t < D) ea[t] = emb[a * D + t];
    if (t == 0) npos = 0;
    slab[t] = labels[t];
    __syncthreads();

    // dist row: d[a][t] = max(|e_a|^2 - 2 e_a.e_t + |e_t|^2, 0)
    {
        const float* ej = emb + t * D;
        float dot = 0.f, sq = 0.f, sqa = 0.f;
        #pragma unroll
        for (int k = 0; k < D; k++) {
            float x = ej[k];
            float y = ea[k];
            dot = fmaf(x, y, dot);
            sq  = fmaf(x, x, sq);
            sqa = fmaf(y, y, sqa);
        }
        drow[t] = fmaxf(sqa - 2.f * dot + sq, 0.f);
    }
    __syncthreads();

    const int la = slab[a];

    // gather positives (label match, p != a)
    if (t != a && slab[t] == la) {
        int idx = atomicAdd(&npos, 1);
        dpos[idx] = drow[t];
    }
    __syncthreads();

    const int np = npos;
    float sum = 0.f, cnt = 0.f;
    if (slab[t] != la) {   // t is a valid negative (implies t != a, t != p)
        const float dn = drow[t];
        for (int p = 0; p < np; p++) {
            float v = dpos[p] - dn + MARGIN;
            if (v > 1e-16f) { sum += v; cnt += 1.f; }
        }
    }

    // block reduction over 12 warps
    const int lane = t & 31;
    const int warp = t >> 5;
    #pragma unroll
    for (int off = 16; off > 0; off >>= 1) {
        sum += __shfl_down_sync(0xFFFFFFFFu, sum, off);
        cnt += __shfl_down_sync(0xFFFFFFFFu, cnt, off);
    }
    if (lane == 0) { rsum[warp] = sum; rcnt[warp] = cnt; }
    __syncthreads();
    if (warp == 0) {
        float s = (lane < 12) ? rsum[lane] : 0.f;
        float c = (lane < 12) ? rcnt[lane] : 0.f;
        #pragma unroll
        for (int off = 16; off > 0; off >>= 1) {
            s += __shfl_down_sync(0xFFFFFFFFu, s, off);
            c += __shfl_down_sync(0xFFFFFFFFu, c, off);
        }
        if (lane == 0) {
            atomicAdd(&g_sum, (double)s);
            atomicAdd(&g_cnt, (double)c);
        }
    }
}

__global__ void final_kernel(float* out) {
    out[0] = (float)(g_sum / (g_cnt + 1e-16));
}

extern "C" void kernel_launch(void* const* d_in, const int* in_sizes, int n_in,
                              void* d_out, int out_size) {
    const float* emb    = (const float*)d_in[0];
    const int*   labels = (const int*)d_in[1];
    float*       out    = (float*)d_out;

    init_kernel<<<1, 1>>>();
    triplet_kernel<<<B, B>>>(emb, labels);
    final_kernel<<<1, 1>>>(out);
}

// round 2
// speedup vs baseline: 6.1111x; 6.1111x over previous
#include <cuda_runtime.h>
#include <cuda_bf16.h>

#define B 384
#define D 128
#define NA 4                  // anchors per block
#define NB (B / NA)           // 96 blocks -> single wave
#define ROWF4 33              // padded row pitch in float4 (132 floats = 528B)
#define MARGIN 0.5f

__device__ float g_psum[NB];
__device__ float g_pcnt[NB];

__global__ __launch_bounds__(B) void triplet_kernel(
    const float* __restrict__ emb,
    const int* __restrict__ labels)
{
    extern __shared__ float4 semb[];      // [B][ROWF4] padded embedding stage
    __shared__ int   slab[B];
    __shared__ float dpos[NA][B];
    __shared__ int   npos[NA];
    __shared__ float sqa_s[NA];
    __shared__ float rsum[12];
    __shared__ float rcnt[12];

    const int t  = threadIdx.x;
    const int ab = blockIdx.x * NA;       // first anchor row of this block

    // ---- stage whole embedding matrix, fully coalesced float4 ----
    const float4* g4 = (const float4*)emb;    // B * 32 float4
    #pragma unroll
    for (int i = 0; i < (B * D / 4) / B; i++) {   // 32 iters
        int g = t + B * i;
        semb[(g >> 5) * ROWF4 + (g & 31)] = g4[g];
    }
    slab[t] = labels[t];
    if (t < NA) npos[t] = 0;
    __syncthreads();

    // ---- thread t owns row t: dot with 4 anchors + own squared norm ----
    float dot[NA] = {0.f, 0.f, 0.f, 0.f};
    float sq = 0.f;
    const float4* xrow = semb + t * ROWF4;
    const float4* arow = semb + ab * ROWF4;

    #pragma unroll 8
    for (int k = 0; k < D / 4; k++) {
        float4 x = xrow[k];
        sq = fmaf(x.x, x.x, fmaf(x.y, x.y, fmaf(x.z, x.z, fmaf(x.w, x.w, sq))));
        #pragma unroll
        for (int aa = 0; aa < NA; aa++) {
            float4 e = arow[aa * ROWF4 + k];   // uniform -> smem broadcast
            dot[aa] = fmaf(x.x, e.x, fmaf(x.y, e.y,
                      fmaf(x.z, e.z, fmaf(x.w, e.w, dot[aa]))));
        }
    }

    // publish anchor squared norms
    if (t >= ab && t < ab + NA) sqa_s[t - ab] = sq;
    __syncthreads();

    // ---- distances for the 4 anchors; gather positives from registers ----
    const int lt = slab[t];
    float dist[NA];
    #pragma unroll
    for (int aa = 0; aa < NA; aa++) {
        dist[aa] = fmaxf(sqa_s[aa] - 2.f * dot[aa] + sq, 0.f);
        if (lt == slab[ab + aa] && t != ab + aa) {
            int idx = atomicAdd(&npos[aa], 1);
            dpos[aa][idx] = dist[aa];
        }
    }
    __syncthreads();

    // ---- thread t as negative candidate for each anchor ----
    float sum = 0.f, cnt = 0.f;
    #pragma unroll
    for (int aa = 0; aa < NA; aa++) {
        if (lt != slab[ab + aa]) {
            const float dn = dist[aa];
            const int np = npos[aa];
            for (int p = 0; p < np; p++) {
                float v = dpos[aa][p] - dn + MARGIN;
                if (v > 1e-16f) { sum += v; cnt += 1.f; }
            }
        }
    }

    // ---- block reduction (12 warps) ----
    const int lane = t & 31;
    const int warp = t >> 5;
    #pragma unroll
    for (int off = 16; off > 0; off >>= 1) {
        sum += __shfl_down_sync(0xFFFFFFFFu, sum, off);
        cnt += __shfl_down_sync(0xFFFFFFFFu, cnt, off);
    }
    if (lane == 0) { rsum[warp] = sum; rcnt[warp] = cnt; }
    __syncthreads();
    if (warp == 0) {
        float s = (lane < 12) ? rsum[lane] : 0.f;
        float c = (lane < 12) ? rcnt[lane] : 0.f;
        #pragma unroll
        for (int off = 16; off > 0; off >>= 1) {
            s += __shfl_down_sync(0xFFFFFFFFu, s, off);
            c += __shfl_down_sync(0xFFFFFFFFu, c, off);
        }
        if (lane == 0) {
            g_psum[blockIdx.x] = s;
            g_pcnt[blockIdx.x] = c;
        }
    }
}

__global__ void final_kernel(float* __restrict__ out) {
    const int t = threadIdx.x;     // 32 threads
    double s = 0.0, c = 0.0;
    for (int i = t; i < NB; i += 32) {
        s += (double)g_psum[i];
        c += (double)g_pcnt[i];
    }
    #pragma unroll
    for (int off = 16; off > 0; off >>= 1) {
        s += __shfl_down_sync(0xFFFFFFFFu, s, off);
        c += __shfl_down_sync(0xFFFFFFFFu, c, off);
    }
    if (t == 0) out[0] = (float)(s / (c + 1e-16));
}

extern "C" void kernel_launch(void* const* d_in, const int* in_sizes, int n_in,
                              void* d_out, int out_size) {
    const float* emb    = (const float*)d_in[0];
    const int*   labels = (const int*)d_in[1];
    float*       out    = (float*)d_out;

    const size_t smem = (size_t)B * ROWF4 * sizeof(float4);   // 202,752 B
    cudaFuncSetAttribute(triplet_kernel,
                         cudaFuncAttributeMaxDynamicSharedMemorySize, (int)smem);

    triplet_kernel<<<NB, B, smem>>>(emb, labels);
    final_kernel<<<1, 32>>>(out);
}

// round 3
// speedup vs baseline: 6.9103x; 1.1308x over previous
#include <cuda_runtime.h>
#include <cuda_bf16.h>

#define B 384
#define D 128
#define NA 3                  // anchors per block
#define NB (B / NA)           // 128 blocks -> single wave on 148 SMs
#define ROWF4 33              // padded row pitch in float4 (132 floats = 528B)
#define MARGIN 0.5f
#define NWARP (B / 32)        // 12

__device__ float g_psum[NB];
__device__ float g_pcnt[NB];
__device__ unsigned int g_ticket;   // zero-initialized; reset by last block

__global__ __launch_bounds__(B) void triplet_kernel(
    const float* __restrict__ emb,
    const int* __restrict__ labels,
    float* __restrict__ out)
{
    extern __shared__ float4 semb[];      // [B][ROWF4] padded embedding stage
    __shared__ int   slab[B];
    __shared__ float dpos[NA][B];
    __shared__ int   npos[NA];
    __shared__ float sqa_s[NA];
    __shared__ float rsum[NWARP];
    __shared__ float rcnt[NWARP];
    __shared__ int   is_last;

    const int t  = threadIdx.x;
    const int ab = blockIdx.x * NA;       // first anchor row of this block

    // ---- stage whole embedding matrix, fully coalesced float4 ----
    const float4* g4 = (const float4*)emb;    // B * 32 float4
    #pragma unroll
    for (int i = 0; i < (B * D / 4) / B; i++) {   // 32 iters
        int g = t + B * i;
        semb[(g >> 5) * ROWF4 + (g & 31)] = g4[g];
    }
    slab[t] = labels[t];
    if (t < NA) npos[t] = 0;
    __syncthreads();

    // ---- thread t owns row t: dot with NA anchors + own squared norm ----
    float dot[NA];
    #pragma unroll
    for (int aa = 0; aa < NA; aa++) dot[aa] = 0.f;
    float sq = 0.f;
    const float4* xrow = semb + t * ROWF4;
    const float4* arow = semb + ab * ROWF4;

    #pragma unroll 8
    for (int k = 0; k < D / 4; k++) {
        float4 x = xrow[k];
        sq = fmaf(x.x, x.x, fmaf(x.y, x.y, fmaf(x.z, x.z, fmaf(x.w, x.w, sq))));
        #pragma unroll
        for (int aa = 0; aa < NA; aa++) {
            float4 e = arow[aa * ROWF4 + k];   // uniform -> smem broadcast
            dot[aa] = fmaf(x.x, e.x, fmaf(x.y, e.y,
                      fmaf(x.z, e.z, fmaf(x.w, e.w, dot[aa]))));
        }
    }

    // publish anchor squared norms
    if (t >= ab && t < ab + NA) sqa_s[t - ab] = sq;
    __syncthreads();

    // ---- distances for the NA anchors; gather positives ----
    const int lt = slab[t];
    float dist[NA];
    #pragma unroll
    for (int aa = 0; aa < NA; aa++) {
        dist[aa] = fmaxf(sqa_s[aa] - 2.f * dot[aa] + sq, 0.f);
        if (lt == slab[ab + aa] && t != ab + aa) {
            int idx = atomicAdd(&npos[aa], 1);
            dpos[aa][idx] = dist[aa];
        }
    }
    __syncthreads();

    // ---- thread t as negative candidate for each anchor ----
    float sum = 0.f, cnt = 0.f;
    #pragma unroll
    for (int aa = 0; aa < NA; aa++) {
        if (lt != slab[ab + aa]) {
            const float dn = dist[aa];
            const int np = npos[aa];
            for (int p = 0; p < np; p++) {
                float v = dpos[aa][p] - dn + MARGIN;
                if (v > 1e-16f) { sum += v; cnt += 1.f; }
            }
        }
    }

    // ---- block reduction (12 warps) ----
    const int lane = t & 31;
    const int warp = t >> 5;
    #pragma unroll
    for (int off = 16; off > 0; off >>= 1) {
        sum += __shfl_down_sync(0xFFFFFFFFu, sum, off);
        cnt += __shfl_down_sync(0xFFFFFFFFu, cnt, off);
    }
    if (lane == 0) { rsum[warp] = sum; rcnt[warp] = cnt; }
    __syncthreads();
    if (warp == 0) {
        float s = (lane < NWARP) ? rsum[lane] : 0.f;
        float c = (lane < NWARP) ? rcnt[lane] : 0.f;
        #pragma unroll
        for (int off = 16; off > 0; off >>= 1) {
            s += __shfl_down_sync(0xFFFFFFFFu, s, off);
            c += __shfl_down_sync(0xFFFFFFFFu, c, off);
        }
        if (lane == 0) {
            g_psum[blockIdx.x] = s;
            g_pcnt[blockIdx.x] = c;
        }
    }

    // ---- last-block-done final reduction (deterministic) ----
    __threadfence();
    if (t == 0) {
        unsigned int tk = atomicAdd(&g_ticket, 1u);
        is_last = (tk == NB - 1);
    }
    __syncthreads();

    if (is_last && warp == 0) {
        __threadfence();
        volatile float* vs = g_psum;
        volatile float* vc = g_pcnt;
        double s = 0.0, c = 0.0;
        #pragma unroll
        for (int i = lane; i < NB; i += 32) {
            s += (double)vs[i];
            c += (double)vc[i];
        }
        #pragma unroll
        for (int off = 16; off > 0; off >>= 1) {
            s += __shfl_down_sync(0xFFFFFFFFu, s, off);
            c += __shfl_down_sync(0xFFFFFFFFu, c, off);
        }
        if (lane == 0) {
            out[0] = (float)(s / (c + 1e-16));
            g_ticket = 0;                       // reset for next graph replay
        }
    }
}

extern "C" void kernel_launch(void* const* d_in, const int* in_sizes, int n_in,
                              void* d_out, int out_size) {
    const float* emb    = (const float*)d_in[0];
    const int*   labels = (const int*)d_in[1];
    float*       out    = (float*)d_out;

    const size_t smem = (size_t)B * ROWF4 * sizeof(float4);   // 202,752 B
    cudaFuncSetAttribute(triplet_kernel,
                         cudaFuncAttributeMaxDynamicSharedMemorySize, (int)smem);

    triplet_kernel<<<NB, B, smem>>>(emb, labels, out);
}